// round 15
// baseline (speedup 1.0000x reference)
#include <cuda_runtime.h>
#include <cuda_bf16.h>
#include <cstdint>

// Problem constants (fixed by setup_inputs)
#define BATCH 4
#define SEQ   2048
#define CDIM  1024
#define NHEAD 16
#define HDIM  64
#define MROWS (BATCH * SEQ)          // 8192
#define K2    2048                   // split-bf16 (hi|lo) doubled K
#define Y_ELEMS ((size_t)MROWS * CDIM)                  // 8,388,608
#define KV_ELEMS ((size_t)BATCH * NHEAD * SEQ * HDIM)   // 8,388,608

// exp2-folded softmax scale: S2 = (0.125 * log2 e) * (q.k)
#define QSCALE 0.18033688011112042f

// ---------------------------------------------------------------------------
// Device scratch (allocation-free per harness rules)
// ---------------------------------------------------------------------------
__device__ __align__(256) __nv_bfloat16 g_a2[(size_t)MROWS * K2];    // A-side (hi|lo): x, then y
__device__ __align__(256) __nv_bfloat16 g_w2[4][(size_t)CDIM * K2];  // Wq,Wk,Wv,Wp (hi|lo), contiguous
__device__ __align__(256) __nv_bfloat16 g_q3[(size_t)KV_ELEMS * 2];  // Q split [B,H,T,(hi64|lo64)]
__device__ __align__(256) __nv_bfloat16 g_k3[(size_t)KV_ELEMS * 2];  // K split [B,H,T,(hi64|lo64)]
__device__ __align__(256) __nv_bfloat16 g_v2[(size_t)KV_ELEMS * 2];  // V split [B,H,T,(hi64|lo64)]

// ---------------------------------------------------------------------------
// PTX helpers (base-target safe: cp.async / ldmatrix / mma.sync only)
// ---------------------------------------------------------------------------
__device__ __forceinline__ uint32_t smem_to_u32(const void* p) {
    uint32_t a;
    asm("{ .reg .u64 t; cvta.to.shared.u64 t, %1; cvt.u32.u64 %0, t; }" : "=r"(a) : "l"(p));
    return a;
}

#define CP_ASYNC16(dst, src) \
    asm volatile("cp.async.cg.shared.global [%0], [%1], 16;" :: "r"(dst), "l"(src))
#define CP_COMMIT() asm volatile("cp.async.commit_group;" ::: "memory")
#define CP_WAIT1()  asm volatile("cp.async.wait_group 1;" ::: "memory")
#define CP_WAIT0()  asm volatile("cp.async.wait_group 0;" ::: "memory")

__device__ __forceinline__ void ldsm_x4(uint32_t addr, uint32_t* r) {
    asm volatile("ldmatrix.sync.aligned.m8n8.x4.shared.b16 {%0,%1,%2,%3}, [%4];"
                 : "=r"(r[0]), "=r"(r[1]), "=r"(r[2]), "=r"(r[3]) : "r"(addr));
}
__device__ __forceinline__ void ldsm_x4_t(uint32_t addr, uint32_t* r) {
    asm volatile("ldmatrix.sync.aligned.m8n8.x4.trans.shared.b16 {%0,%1,%2,%3}, [%4];"
                 : "=r"(r[0]), "=r"(r[1]), "=r"(r[2]), "=r"(r[3]) : "r"(addr));
}

__device__ __forceinline__ void mma16816(float* c, const uint32_t* a, const uint32_t* b) {
    asm volatile(
        "mma.sync.aligned.m16n8k16.row.col.f32.bf16.bf16.f32 "
        "{%0,%1,%2,%3}, {%4,%5,%6,%7}, {%8,%9}, {%0,%1,%2,%3};"
        : "+f"(c[0]), "+f"(c[1]), "+f"(c[2]), "+f"(c[3])
        : "r"(a[0]), "r"(a[1]), "r"(a[2]), "r"(a[3]), "r"(b[0]), "r"(b[1]));
}

// Split two fp32 into packed bf16 hi-pair / lo-pair (elem0 in low half).
__device__ __forceinline__ void split2(float x0, float x1, uint32_t& hp, uint32_t& lp) {
    __nv_bfloat16 h0 = __float2bfloat16(x0);
    __nv_bfloat16 h1 = __float2bfloat16(x1);
    float r0 = x0 - __bfloat162float(h0);
    float r1 = x1 - __bfloat162float(h1);
    __nv_bfloat162 hh(h0, h1);
    __nv_bfloat162 ll(__float2bfloat16(r0), __float2bfloat16(r1));
    hp = *reinterpret_cast<uint32_t*>(&hh);
    lp = *reinterpret_cast<uint32_t*>(&ll);
}

// ---------------------------------------------------------------------------
// Split conversions: [rows][1024] fp32 -> [rows][2048] bf16 (hi | lo).
// ---------------------------------------------------------------------------
__global__ __launch_bounds__(256) void conv_split_x_kernel(
    const float* __restrict__ src, __nv_bfloat16* __restrict__ dst, int total2)
{
    int i = blockIdx.x * blockDim.x + threadIdx.x;
    if (i >= total2) return;
    int r = i >> 9;
    int c = (i & 511) << 1;
    float2 v = reinterpret_cast<const float2*>(src)[i];
    uint32_t hp, lp;
    split2(v.x, v.y, hp, lp);
    uint32_t* base = reinterpret_cast<uint32_t*>(dst + (size_t)r * K2 + c);
    base[0]   = hp;
    base[512] = lp;
}

__global__ __launch_bounds__(256) void conv_split_w_kernel(
    const float* __restrict__ Wq, const float* __restrict__ Wk,
    const float* __restrict__ Wv, const float* __restrict__ Wp,
    __nv_bfloat16* __restrict__ dst)   // g_w2 base; 4 matrices contiguous
{
    int i = blockIdx.x * blockDim.x + threadIdx.x;   // < 4*1024*512
    int r = i >> 9;                 // global row 0..4095
    int c = (i & 511) << 1;
    int wsel = r >> 10;
    int row  = r & 1023;
    const float* src = (wsel == 0) ? Wq : (wsel == 1) ? Wk : (wsel == 2) ? Wv : Wp;
    float2 v = reinterpret_cast<const float2*>(src)[row * 512 + (i & 511)];
    uint32_t hp, lp;
    split2(v.x, v.y, hp, lp);
    uint32_t* base = reinterpret_cast<uint32_t*>(
        dst + (size_t)wsel * CDIM * K2 + (size_t)row * K2 + c);
    base[0]   = hp;
    base[512] = lp;
}

// ---------------------------------------------------------------------------
// mma.sync split-bf16 GEMM with fragment reuse:
//   acc = ah.bh + al.bh + ah.bl    (hi|lo packed in one 128B smem row:
//   chunks 0-3 = hi 32 dims, chunks 4-7 = lo 32 dims; 32-dim K-chunks)
// 128x128 tile, 256 threads, warp tile 32x64, 3-stage cp.async, 2 CTA/SM.
// mode 0: proj -> out0 fp32 [M,1024] (grid.x = 8)
// mode 1: fused QKV over Nrows=3072 (grid.x = 24):
//   Q -> (val+bq)*QSCALE split (hi|lo) into q3 [B,H,T,128]
//   K -> val+bk fp32 into out0 [B,H,T,D] + split (hi|lo) into k3
//   V -> val+bv fp32 into out1 [B,H,T,D] + split (hi|lo) into v2
// ---------------------------------------------------------------------------
#define GSM_TOTAL 98304   // 3 stages x (16KB A + 16KB B)

__global__ __launch_bounds__(256) void gemm_bf16_kernel(
    const __nv_bfloat16* __restrict__ A2, const __nv_bfloat16* __restrict__ W2,
    const float* __restrict__ b0, const float* __restrict__ b1,
    const float* __restrict__ b2,
    float* __restrict__ out0, float* __restrict__ out1,
    __nv_bfloat16* __restrict__ q3, __nv_bfloat16* __restrict__ k3,
    __nv_bfloat16* __restrict__ v2,
    int mode)
{
    extern __shared__ char smem[];
    const uint32_t sA = smem_to_u32(smem);      // 3 x 16KB
    const uint32_t sB = sA + 49152;             // 3 x 16KB

    const int tid  = threadIdx.x;
    const int wid  = tid >> 5;
    const int lane = tid & 31;
    const int wm = wid >> 1;
    const int wn = wid & 1;
    const int mbase = blockIdx.y * 128;
    const int nbase = blockIdx.x * 128;

    const __nv_bfloat16* Ag = A2 + (size_t)mbase * K2;
    const __nv_bfloat16* Bg = W2 + (size_t)nbase * K2;

    float acc[2][8][4];
    #pragma unroll
    for (int i = 0; i < 2; i++)
        #pragma unroll
        for (int j = 0; j < 8; j++)
            #pragma unroll
            for (int q = 0; q < 4; q++) acc[i][j][q] = 0.f;

    const int NITER = 32;          // 1024 dims / 32 per chunk

    // stage row = [hi 32 dims (chunks 0-3) | lo 32 dims (chunks 4-7)]
    auto load_chunk = [&](int it, int slot) {
        const int kk = it * 32;
        const uint32_t aBase = sA + slot * 16384;
        const uint32_t bBase = sB + slot * 16384;
        #pragma unroll
        for (int t = 0; t < 4; t++) {
            int idx = tid + t * 256;       // 0..1023
            int row = idx >> 3, s = idx & 7;
            int col = (s < 4) ? (kk + s * 8) : (1024 + kk + (s - 4) * 8);
            uint32_t doff = row * 128 + ((s ^ (row & 7)) << 4);
            CP_ASYNC16(aBase + doff, Ag + (size_t)row * K2 + col);
            CP_ASYNC16(bBase + doff, Bg + (size_t)row * K2 + col);
        }
    };

    load_chunk(0, 0); CP_COMMIT();
    load_chunk(1, 1); CP_COMMIT();

    int slot = 0;
    for (int it = 0; it < NITER; ++it) {
        CP_WAIT1();
        __syncthreads();
        int nslot = slot + 2; if (nslot >= 3) nslot -= 3;
        if (it + 2 < NITER) load_chunk(it + 2, nslot);
        CP_COMMIT();

        const uint32_t aBase = sA + slot * 16384;
        const uint32_t bBase = sB + slot * 16384;

        #pragma unroll
        for (int ks = 0; ks < 2; ks++) {
            uint32_t ah[2][4], al[2][4];
            #pragma unroll
            for (int mi = 0; mi < 2; mi++) {
                int row = wm * 32 + mi * 16 + (lane & 15);
                int chunk = 2 * ks + (lane >> 4);          // 0..3 (hi)
                uint32_t aoff = aBase + row * 128;
                ldsm_x4(aoff + (((chunk)     ^ (row & 7)) << 4), ah[mi]);
                ldsm_x4(aoff + (((chunk + 4) ^ (row & 7)) << 4), al[mi]);
            }
            uint32_t bf[8][2];
            // bh: used by ah and al
            #pragma unroll
            for (int ni = 0; ni < 4; ni++) {
                int row = wn * 64 + ni * 16 + ((lane >> 4) << 3) + (lane & 7);
                int chunk = 2 * ks + ((lane >> 3) & 1);    // 0..3 (hi)
                uint32_t r4[4];
                ldsm_x4(bBase + row * 128 + ((chunk ^ (row & 7)) << 4), r4);
                bf[2 * ni][0] = r4[0]; bf[2 * ni][1] = r4[1];
                bf[2 * ni + 1][0] = r4[2]; bf[2 * ni + 1][1] = r4[3];
            }
            #pragma unroll
            for (int mi = 0; mi < 2; mi++)
                #pragma unroll
                for (int nj = 0; nj < 8; nj++) {
                    mma16816(acc[mi][nj], ah[mi], bf[nj]);
                    mma16816(acc[mi][nj], al[mi], bf[nj]);
                }
            // bl: used by ah only
            #pragma unroll
            for (int ni = 0; ni < 4; ni++) {
                int row = wn * 64 + ni * 16 + ((lane >> 4) << 3) + (lane & 7);
                int chunk = 2 * ks + ((lane >> 3) & 1) + 4;  // 4..7 (lo)
                uint32_t r4[4];
                ldsm_x4(bBase + row * 128 + ((chunk ^ (row & 7)) << 4), r4);
                bf[2 * ni][0] = r4[0]; bf[2 * ni][1] = r4[1];
                bf[2 * ni + 1][0] = r4[2]; bf[2 * ni + 1][1] = r4[3];
            }
            #pragma unroll
            for (int mi = 0; mi < 2; mi++)
                #pragma unroll
                for (int nj = 0; nj < 8; nj++)
                    mma16816(acc[mi][nj], ah[mi], bf[nj]);
        }
        if (++slot >= 3) slot = 0;
    }

    // ---- epilogue ----
    const int which = nbase >> 10;
    const float* bias = (mode == 0) ? b0 : (which == 0 ? b0 : (which == 1 ? b1 : b2));
    const int qr = lane >> 2;
    const int qc = (lane & 3) * 2;
    #pragma unroll
    for (int mi = 0; mi < 2; mi++) {
        #pragma unroll
        for (int half = 0; half < 2; half++) {
            int m = mbase + wm * 32 + mi * 16 + qr + half * 8;
            int b_ = m >> 11, t = m & 2047;
            #pragma unroll
            for (int nj = 0; nj < 8; nj++) {
                int ng = nbase + wn * 64 + nj * 8 + qc;
                int n  = ng & 1023;
                float vx = acc[mi][nj][half * 2 + 0] + bias[n];
                float vy = acc[mi][nj][half * 2 + 1] + bias[n + 1];
                if (mode == 0) {
                    float2 o{vx, vy};
                    *reinterpret_cast<float2*>(out0 + (size_t)m * CDIM + n) = o;
                } else {
                    int h = n >> 6, d = n & 63;
                    size_t bht = ((size_t)(b_ * NHEAD + h)) * SEQ + t;
                    size_t base2 = bht * 128 + d;
                    if (which == 0) {
                        vx *= QSCALE; vy *= QSCALE;
                        uint32_t hp, lp;
                        split2(vx, vy, hp, lp);
                        *reinterpret_cast<uint32_t*>(q3 + base2)      = hp;
                        *reinterpret_cast<uint32_t*>(q3 + base2 + 64) = lp;
                    } else if (which == 1) {
                        float2 o{vx, vy};
                        *reinterpret_cast<float2*>(out0 + bht * HDIM + d) = o;
                        uint32_t hp, lp;
                        split2(vx, vy, hp, lp);
                        *reinterpret_cast<uint32_t*>(k3 + base2)      = hp;
                        *reinterpret_cast<uint32_t*>(k3 + base2 + 64) = lp;
                    } else {
                        float2 o{vx, vy};
                        *reinterpret_cast<float2*>(out1 + bht * HDIM + d) = o;
                        uint32_t hp, lp;
                        split2(vx, vy, hp, lp);
                        *reinterpret_cast<uint32_t*>(v2 + base2)      = hp;
                        *reinterpret_cast<uint32_t*>(v2 + base2 + 64) = lp;
                    }
                }
            }
        }
    }
}

// ---------------------------------------------------------------------------
// HMMA causal flash attention (R14 — validated: tensor 58%), software-
// pipelined, max-free softmax, full 3-product S with fragment reuse.
// BM=128 / BN=64, 256 threads. Epilogue writes (hi|lo) rows of A2 [M][2048].
// smem: Q 2x16K | K ring 3x16K | V ring 3x16K = 128KB.
// ---------------------------------------------------------------------------
#define QS_OFF   0
#define KS_OFF   32768
#define VS_OFF   81920
#define ATTN_SMEM 131072

__global__ __launch_bounds__(256) void attn_kernel(
    const __nv_bfloat16* __restrict__ Q3, const __nv_bfloat16* __restrict__ K3g,
    const __nv_bfloat16* __restrict__ V2, __nv_bfloat16* __restrict__ Yd)
{
    extern __shared__ char smem[];
    const uint32_t sm = smem_to_u32(smem);
    const uint32_t QS = sm + QS_OFF;
    const uint32_t KS = sm + KS_OFF;
    const uint32_t VS = sm + VS_OFF;

    const int tid = threadIdx.x;
    const int w = tid >> 5;
    const int lane = tid & 31;
    const int qt = (int)gridDim.x - 1 - (int)blockIdx.x;   // long CTAs first
    const int bh = blockIdx.y;
    const int qbase = qt * 128;

    const __nv_bfloat16* Qg = Q3 + ((size_t)bh * SEQ + qbase) * 128;
    const __nv_bfloat16* Kg = K3g + (size_t)bh * SEQ * 128;
    const __nv_bfloat16* Vg = V2 + (size_t)bh * SEQ * 128;

    auto load_q = [&]() {
        #pragma unroll
        for (int i = 0; i < 8; i++) {
            int g = tid + i * 256;          // 0..2047
            int r = g & 127, bc = g >> 7;   // bc 0..15
            int b = bc >> 3, c = bc & 7;
            const __nv_bfloat16* src = Qg + (size_t)r * 128 + b * 64 + c * 8;
            uint32_t dst = QS + b * 16384 + r * 128 + ((c ^ (r & 7)) << 4);
            CP_ASYNC16(dst, src);
        }
    };
    auto load_k = [&](int jt, int slot) {
        const __nv_bfloat16* base = Kg + (size_t)jt * 64 * 128;
        uint32_t kb = KS + slot * 16384;    // [kh 8K | kl 8K]
        #pragma unroll
        for (int i = 0; i < 4; i++) {
            int g = tid + i * 256;          // 0..1023
            int r = g >> 4, c = g & 15;
            const __nv_bfloat16* src = base + (size_t)r * 128 + c * 8;
            int cc = c & 7;
            uint32_t half = (c >> 3) * 8192;
            uint32_t dst = kb + half + r * 128 + ((cc ^ (r & 7)) << 4);
            CP_ASYNC16(dst, src);
        }
    };
    auto load_v = [&](int jt, int slot) {
        const __nv_bfloat16* base = Vg + (size_t)jt * 64 * 128;
        uint32_t vb = VS + slot * 16384;    // [vh 8K | vl 8K]
        #pragma unroll
        for (int i = 0; i < 4; i++) {
            int g = tid + i * 256;
            int r = g >> 4, c = g & 15;
            const __nv_bfloat16* src = base + (size_t)r * 128 + c * 8;
            int cc = c & 7;
            uint32_t half = (c >> 3) * 8192;
            uint32_t dst = vb + half + r * 128 + ((cc ^ (r & 7)) << 4);
            CP_ASYNC16(dst, src);
        }
    };

    float o[8][4];
    #pragma unroll
    for (int j = 0; j < 8; j++)
        #pragma unroll
        for (int q = 0; q < 4; q++) o[j][q] = 0.f;
    float li0 = 0.f, li1 = 0.f;     // per-thread partial row sums

    const int jmax = 2 * qt + 1;

    // S = qh.kh + ql.kh + qh.kl with K fragments loaded once per k-step
    auto mma_S = [&](float (&sd)[8][4], int slot) {
        #pragma unroll
        for (int j = 0; j < 8; j++)
            #pragma unroll
            for (int q = 0; q < 4; q++) sd[j][q] = 0.f;
        const uint32_t kb = KS + slot * 16384;
        #pragma unroll
        for (int ks = 0; ks < 4; ks++) {
            uint32_t ah[4], al[4];
            {
                int row = w * 16 + (lane & 15);
                int chunk = 2 * ks + (lane >> 4);
                uint32_t qoff = row * 128 + ((chunk ^ (row & 7)) << 4);
                ldsm_x4(QS + qoff, ah);
                ldsm_x4(QS + 16384 + qoff, al);
            }
            uint32_t bf[8][2];
            // kh half: used by both ah and al
            #pragma unroll
            for (int ni = 0; ni < 4; ni++) {
                int row = ni * 16 + ((lane >> 4) << 3) + (lane & 7);
                int chunk = 2 * ks + ((lane >> 3) & 1);
                uint32_t r4[4];
                ldsm_x4(kb + row * 128 + ((chunk ^ (row & 7)) << 4), r4);
                bf[2 * ni][0] = r4[0]; bf[2 * ni][1] = r4[1];
                bf[2 * ni + 1][0] = r4[2]; bf[2 * ni + 1][1] = r4[3];
            }
            #pragma unroll
            for (int nj = 0; nj < 8; nj++) {
                mma16816(sd[nj], ah, bf[nj]);
                mma16816(sd[nj], al, bf[nj]);
            }
            // kl half: used by ah only
            #pragma unroll
            for (int ni = 0; ni < 4; ni++) {
                int row = ni * 16 + ((lane >> 4) << 3) + (lane & 7);
                int chunk = 2 * ks + ((lane >> 3) & 1);
                uint32_t r4[4];
                ldsm_x4(kb + 8192 + row * 128 + ((chunk ^ (row & 7)) << 4), r4);
                bf[2 * ni][0] = r4[0]; bf[2 * ni][1] = r4[1];
                bf[2 * ni + 1][0] = r4[2]; bf[2 * ni + 1][1] = r4[3];
            }
            #pragma unroll
            for (int nj = 0; nj < 8; nj++)
                mma16816(sd[nj], ah, bf[nj]);
        }
    };

    // softmax (max-free) + PV (full 3-pass split) for tile cj
    auto consume = [&](float (&s)[8][4], int cj) {
        if (cj * 64 + 63 > qbase + w * 16) {
            const int gr = qbase + w * 16 + (lane >> 2);
            const int cb = cj * 64 + 2 * (lane & 3);
            #pragma unroll
            for (int nj = 0; nj < 8; nj++) {
                int c0 = cb + nj * 8;
                if (c0 > gr)     s[nj][0] = -1e30f;
                if (c0 + 1 > gr) s[nj][1] = -1e30f;
                if (c0 > gr + 8)     s[nj][2] = -1e30f;
                if (c0 + 1 > gr + 8) s[nj][3] = -1e30f;
            }
        }
        #pragma unroll
        for (int nj = 0; nj < 8; nj++) {
            s[nj][0] = exp2f(s[nj][0]); li0 += s[nj][0];
            s[nj][1] = exp2f(s[nj][1]); li0 += s[nj][1];
            s[nj][2] = exp2f(s[nj][2]); li1 += s[nj][2];
            s[nj][3] = exp2f(s[nj][3]); li1 += s[nj][3];
        }
        const uint32_t vb = VS + (cj % 3) * 16384;
        #pragma unroll
        for (int kc = 0; kc < 4; kc++) {
            uint32_t ah[4], al[4];
            split2(s[2 * kc][0],     s[2 * kc][1],     ah[0], al[0]);
            split2(s[2 * kc][2],     s[2 * kc][3],     ah[1], al[1]);
            split2(s[2 * kc + 1][0], s[2 * kc + 1][1], ah[2], al[2]);
            split2(s[2 * kc + 1][2], s[2 * kc + 1][3], ah[3], al[3]);
            #pragma unroll
            for (int dj2 = 0; dj2 < 4; dj2++) {
                int mm = lane >> 3, j = lane & 7;
                int row = kc * 16 + (mm & 1) * 8 + j;
                int chunk = 2 * dj2 + (mm >> 1);
                uint32_t off = row * 128 + ((chunk ^ (row & 7)) << 4);
                uint32_t bh4[4], bl4[4];
                ldsm_x4_t(vb + off, bh4);
                ldsm_x4_t(vb + 8192 + off, bl4);
                mma16816(o[2 * dj2],     ah, &bh4[0]);
                mma16816(o[2 * dj2 + 1], ah, &bh4[2]);
                mma16816(o[2 * dj2],     al, &bh4[0]);
                mma16816(o[2 * dj2 + 1], al, &bh4[2]);
                mma16816(o[2 * dj2],     ah, &bl4[0]);
                mma16816(o[2 * dj2 + 1], ah, &bl4[2]);
            }
        }
    };

    auto iter = [&](int jt, float (&cur)[8][4], float (&nxt)[8][4]) {
        CP_WAIT1();
        __syncthreads();
        if (jt + 2 <= jmax) load_k(jt + 2, (jt + 2) % 3);
        if (jt + 1 <= jmax) load_v(jt + 1, (jt + 1) % 3);
        CP_COMMIT();
        mma_S(nxt, jt % 3);
        if (jt > 0) consume(cur, jt - 1);
    };

    load_q(); load_k(0, 0); CP_COMMIT();
    load_k(1, 1); load_v(0, 0); CP_COMMIT();

    float s0[8][4], s1[8][4];
    for (int jt = 0; jt <= jmax; jt += 2) {
        iter(jt,     s1, s0);
        iter(jt + 1, s0, s1);
    }
    CP_WAIT0();
    __syncthreads();
    consume(s1, jmax);

    // ---- single li reduction, normalize + store (hi|lo) rows of A2 ----
    li0 += __shfl_xor_sync(0xffffffffu, li0, 1);
    li0 += __shfl_xor_sync(0xffffffffu, li0, 2);
    li1 += __shfl_xor_sync(0xffffffffu, li1, 1);
    li1 += __shfl_xor_sync(0xffffffffu, li1, 2);

    const int b_ = bh >> 4;
    const int h  = bh & 15;
    const float inv0 = 1.f / li0, inv1 = 1.f / li1;
    const int t0 = qbase + w * 16 + (lane >> 2);
    const int cb = h * HDIM + 2 * (lane & 3);
    const size_t m0 = (size_t)b_ * SEQ + t0;
    #pragma unroll
    for (int dj = 0; dj < 8; dj++) {
        int col = cb + dj * 8;
        uint32_t hp, lp;
        split2(o[dj][0] * inv0, o[dj][1] * inv0, hp, lp);
        __nv_bfloat16* p0 = Yd + m0 * K2 + col;
        *reinterpret_cast<uint32_t*>(p0)        = hp;
        *reinterpret_cast<uint32_t*>(p0 + 1024) = lp;
        split2(o[dj][2] * inv1, o[dj][3] * inv1, hp, lp);
        __nv_bfloat16* p1 = Yd + (m0 + 8) * K2 + col;
        *reinterpret_cast<uint32_t*>(p1)        = hp;
        *reinterpret_cast<uint32_t*>(p1 + 1024) = lp;
    }
}

// ---------------------------------------------------------------------------
// Launch graph
// d_in: x, Wq, bq, Wk, bk, Wv, bv, Wp, bp
// d_out: [ y | present_k | present_v ]
// ---------------------------------------------------------------------------
extern "C" void kernel_launch(void* const* d_in, const int* in_sizes, int n_in,
                              void* d_out, int out_size)
{
    const float* x  = (const float*)d_in[0];
    const float* Wq = (const float*)d_in[1];
    const float* bq = (const float*)d_in[2];
    const float* Wk = (const float*)d_in[3];
    const float* bk = (const float*)d_in[4];
    const float* Wv = (const float*)d_in[5];
    const float* bv = (const float*)d_in[6];
    const float* Wp = (const float*)d_in[7];
    const float* bp = (const float*)d_in[8];

    float* out  = (float*)d_out;
    float* kout = out + Y_ELEMS;
    float* vout = out + Y_ELEMS + KV_ELEMS;

    __nv_bfloat16 *a2 = nullptr, *w2 = nullptr, *q3 = nullptr, *k3 = nullptr, *v2 = nullptr;
    cudaGetSymbolAddress((void**)&a2, g_a2);
    cudaGetSymbolAddress((void**)&w2, g_w2);
    cudaGetSymbolAddress((void**)&q3, g_q3);
    cudaGetSymbolAddress((void**)&k3, g_k3);
    cudaGetSymbolAddress((void**)&v2, g_v2);

    cudaFuncSetAttribute(gemm_bf16_kernel,
                         cudaFuncAttributeMaxDynamicSharedMemorySize, GSM_TOTAL);
    cudaFuncSetAttribute(attn_kernel,
                         cudaFuncAttributeMaxDynamicSharedMemorySize, ATTN_SMEM);

    // All 4 weight conversions in ONE launch; x conversion separate.
    {
        int total2w = 4 * CDIM * 512;
        conv_split_w_kernel<<<total2w / 256, 256>>>(Wq, Wk, Wv, Wp, w2);
        int total2x = MROWS * 512;
        conv_split_x_kernel<<<(total2x + 255) / 256, 256>>>(x, a2, total2x);
    }

    // Fused QKV GEMM: N = 3072 over contiguous Wq|Wk|Wv (tile 128x128)
    gemm_bf16_kernel<<<dim3(24, MROWS / 128), 256, GSM_TOTAL>>>(
        a2, w2, bq, bk, bv, kout, vout, q3, k3, v2, 1);

    // Attention (pipelined, max-free, full 3-product S with fragment reuse)
    attn_kernel<<<dim3(SEQ / 128, BATCH * NHEAD), 256, ATTN_SMEM>>>(q3, k3, v2, a2);

    // Output projection (mode 0)
    gemm_bf16_kernel<<<dim3(8, MROWS / 128), 256, GSM_TOTAL>>>(
        a2, w2 + 3 * (size_t)CDIM * K2, bp, nullptr, nullptr,
        out, nullptr, nullptr, nullptr, nullptr, 0);
}

// round 16
// speedup vs baseline: 1.0491x; 1.0491x over previous
#include <cuda_runtime.h>
#include <cuda_bf16.h>
#include <cstdint>

// Problem constants (fixed by setup_inputs)
#define BATCH 4
#define SEQ   2048
#define CDIM  1024
#define NHEAD 16
#define HDIM  64
#define MROWS (BATCH * SEQ)          // 8192
#define K3    3072                   // split-bf16 tripled K (projections)
#define Y_ELEMS ((size_t)MROWS * CDIM)                  // 8,388,608
#define KV_ELEMS ((size_t)BATCH * NHEAD * SEQ * HDIM)   // 8,388,608

// exp2-folded softmax scale: S2 = (0.125 * log2 e) * (q.k)
#define QSCALE 0.18033688011112042f

// ---------------------------------------------------------------------------
// Device scratch (allocation-free per harness rules)
// ---------------------------------------------------------------------------
__device__ __align__(256) __nv_bfloat16 g_a3[(size_t)MROWS * K3];    // A-side split (x, then y)
__device__ __align__(256) __nv_bfloat16 g_w3[4][(size_t)CDIM * K3];  // Wq,Wk,Wv,Wp split (contiguous)
__device__ __align__(256) __nv_bfloat16 g_q3[(size_t)KV_ELEMS * 2];  // Q split [B,H,T,(hi64|lo64)]
__device__ __align__(256) __nv_bfloat16 g_k3[(size_t)KV_ELEMS * 2];  // K split [B,H,T,(hi64|lo64)]
__device__ __align__(256) __nv_bfloat16 g_v2[(size_t)KV_ELEMS * 2];  // V split [B,H,T,(hi64|lo64)]

// ---------------------------------------------------------------------------
// PTX helpers (base-target safe: cp.async / ldmatrix / mma.sync only)
// ---------------------------------------------------------------------------
__device__ __forceinline__ uint32_t smem_to_u32(const void* p) {
    uint32_t a;
    asm("{ .reg .u64 t; cvta.to.shared.u64 t, %1; cvt.u32.u64 %0, t; }" : "=r"(a) : "l"(p));
    return a;
}

#define CP_ASYNC16(dst, src) \
    asm volatile("cp.async.cg.shared.global [%0], [%1], 16;" :: "r"(dst), "l"(src))
#define CP_COMMIT() asm volatile("cp.async.commit_group;" ::: "memory")
#define CP_WAIT1()  asm volatile("cp.async.wait_group 1;" ::: "memory")
#define CP_WAIT0()  asm volatile("cp.async.wait_group 0;" ::: "memory")

__device__ __forceinline__ void ldsm_x4(uint32_t addr, uint32_t* r) {
    asm volatile("ldmatrix.sync.aligned.m8n8.x4.shared.b16 {%0,%1,%2,%3}, [%4];"
                 : "=r"(r[0]), "=r"(r[1]), "=r"(r[2]), "=r"(r[3]) : "r"(addr));
}
__device__ __forceinline__ void ldsm_x4_t(uint32_t addr, uint32_t* r) {
    asm volatile("ldmatrix.sync.aligned.m8n8.x4.trans.shared.b16 {%0,%1,%2,%3}, [%4];"
                 : "=r"(r[0]), "=r"(r[1]), "=r"(r[2]), "=r"(r[3]) : "r"(addr));
}

__device__ __forceinline__ void mma16816(float* c, const uint32_t* a, const uint32_t* b) {
    asm volatile(
        "mma.sync.aligned.m16n8k16.row.col.f32.bf16.bf16.f32 "
        "{%0,%1,%2,%3}, {%4,%5,%6,%7}, {%8,%9}, {%0,%1,%2,%3};"
        : "+f"(c[0]), "+f"(c[1]), "+f"(c[2]), "+f"(c[3])
        : "r"(a[0]), "r"(a[1]), "r"(a[2]), "r"(a[3]), "r"(b[0]), "r"(b[1]));
}

// Split two fp32 into packed bf16 hi-pair / lo-pair (elem0 in low half).
__device__ __forceinline__ void split2(float x0, float x1, uint32_t& hp, uint32_t& lp) {
    __nv_bfloat16 h0 = __float2bfloat16(x0);
    __nv_bfloat16 h1 = __float2bfloat16(x1);
    float r0 = x0 - __bfloat162float(h0);
    float r1 = x1 - __bfloat162float(h1);
    __nv_bfloat162 hh(h0, h1);
    __nv_bfloat162 ll(__float2bfloat16(r0), __float2bfloat16(r1));
    hp = *reinterpret_cast<uint32_t*>(&hh);
    lp = *reinterpret_cast<uint32_t*>(&ll);
}

// ---------------------------------------------------------------------------
// Split-bf16 conversions: [rows][1024] fp32 -> [rows][3072] bf16.
// x: (hi, lo, hi). Weights (all four in one launch): (hi, hi, lo).
// ---------------------------------------------------------------------------
__global__ __launch_bounds__(256) void conv_split_x_kernel(
    const float* __restrict__ src, __nv_bfloat16* __restrict__ dst, int total2)
{
    int i = blockIdx.x * blockDim.x + threadIdx.x;
    if (i >= total2) return;
    int r = i >> 9;
    int c = (i & 511) << 1;
    float2 v = reinterpret_cast<const float2*>(src)[i];
    uint32_t hp, lp;
    split2(v.x, v.y, hp, lp);
    uint32_t* base = reinterpret_cast<uint32_t*>(dst + (size_t)r * K3 + c);
    base[0]    = hp;
    base[512]  = lp;
    base[1024] = hp;
}

__global__ __launch_bounds__(256) void conv_split_w_kernel(
    const float* __restrict__ Wq, const float* __restrict__ Wk,
    const float* __restrict__ Wv, const float* __restrict__ Wp,
    __nv_bfloat16* __restrict__ dst)   // g_w3 base; 4 matrices contiguous
{
    int i = blockIdx.x * blockDim.x + threadIdx.x;   // < 4*1024*512
    int r = i >> 9;                 // global row 0..4095
    int c = (i & 511) << 1;
    int wsel = r >> 10;
    int row  = r & 1023;
    const float* src = (wsel == 0) ? Wq : (wsel == 1) ? Wk : (wsel == 2) ? Wv : Wp;
    float2 v = reinterpret_cast<const float2*>(src)[row * 512 + (i & 511)];
    uint32_t hp, lp;
    split2(v.x, v.y, hp, lp);
    uint32_t* base = reinterpret_cast<uint32_t*>(
        dst + (size_t)wsel * CDIM * K3 + (size_t)row * K3 + c);
    base[0]    = hp;
    base[512]  = hp;
    base[1024] = lp;
}

// ---------------------------------------------------------------------------
// mma.sync split-bf16 GEMM: 128x128 tile, 3-stage cp.async (R14 — validated).
// mode 0: proj -> out0 fp32 [M,1024] (grid.x = 8)
// mode 1: fused QKV over Nrows=3072 (grid.x = 24):
//   Q -> (val+bq)*QSCALE split (hi|lo) into q3 [B,H,T,128]
//   K -> val+bk fp32 into out0 [B,H,T,D] + split (hi|lo) into k3 [B,H,T,128]
//   V -> val+bv fp32 into out1 [B,H,T,D] + split (hi|lo) into v2 [B,H,T,128]
// ---------------------------------------------------------------------------
#define GSM_TOTAL 98304   // 3 stages x (16KB A + 16KB B)

__global__ __launch_bounds__(256) void gemm_bf16_kernel(
    const __nv_bfloat16* __restrict__ A3, const __nv_bfloat16* __restrict__ W3,
    const float* __restrict__ b0, const float* __restrict__ b1,
    const float* __restrict__ b2,
    float* __restrict__ out0, float* __restrict__ out1,
    __nv_bfloat16* __restrict__ q3, __nv_bfloat16* __restrict__ k3,
    __nv_bfloat16* __restrict__ v2,
    int mode)
{
    extern __shared__ char smem[];
    const uint32_t sA = smem_to_u32(smem);      // 3 x 16KB
    const uint32_t sB = sA + 49152;             // 3 x 16KB

    const int tid  = threadIdx.x;
    const int wid  = tid >> 5;
    const int lane = tid & 31;
    const int wm = wid >> 1;
    const int wn = wid & 1;
    const int mbase = blockIdx.y * 128;
    const int nbase = blockIdx.x * 128;

    const __nv_bfloat16* Ag = A3 + (size_t)mbase * K3;
    const __nv_bfloat16* Bg = W3 + (size_t)nbase * K3;

    float acc[2][8][4];
    #pragma unroll
    for (int i = 0; i < 2; i++)
        #pragma unroll
        for (int j = 0; j < 8; j++)
            #pragma unroll
            for (int q = 0; q < 4; q++) acc[i][j][q] = 0.f;

    const int lr  = tid & 7;
    const int lc  = (tid >> 3) & 7;
    const int lb0 = tid >> 6;

    const int NITER = K3 / 64;     // 48

    auto load_chunk = [&](int it, int slot) {
        const size_t kofs = (size_t)it * 64;
        const uint32_t aBase = sA + slot * 16384;
        const uint32_t bBase = sB + slot * 16384;
        #pragma unroll
        for (int t = 0; t < 4; t++) {
            int row = (lb0 + t * 4) * 8 + lr;
            uint32_t doff = row * 128 + ((lc ^ lr) << 4);
            const __nv_bfloat16* asrc = Ag + (size_t)row * K3 + kofs + lc * 8;
            const __nv_bfloat16* bsrc = Bg + (size_t)row * K3 + kofs + lc * 8;
            CP_ASYNC16(aBase + doff, asrc);
            CP_ASYNC16(bBase + doff, bsrc);
        }
    };

    load_chunk(0, 0); CP_COMMIT();
    load_chunk(1, 1); CP_COMMIT();

    int slot = 0;
    for (int it = 0; it < NITER; ++it) {
        CP_WAIT1();
        __syncthreads();
        int nslot = slot + 2; if (nslot >= 3) nslot -= 3;
        if (it + 2 < NITER) load_chunk(it + 2, nslot);
        CP_COMMIT();

        const uint32_t aBase = sA + slot * 16384;
        const uint32_t bBase = sB + slot * 16384;

        #pragma unroll
        for (int ks = 0; ks < 4; ks++) {
            uint32_t af[2][4];
            #pragma unroll
            for (int mi = 0; mi < 2; mi++) {
                int row = wm * 32 + mi * 16 + (lane & 15);
                int chunk = 2 * ks + (lane >> 4);
                uint32_t addr = aBase + row * 128 + ((chunk ^ (row & 7)) << 4);
                ldsm_x4(addr, af[mi]);
            }
            uint32_t bf[8][2];
            #pragma unroll
            for (int ni = 0; ni < 4; ni++) {
                int row = wn * 64 + ni * 16 + ((lane >> 4) << 3) + (lane & 7);
                int chunk = 2 * ks + ((lane >> 3) & 1);
                uint32_t addr = bBase + row * 128 + ((chunk ^ (row & 7)) << 4);
                uint32_t r4[4];
                ldsm_x4(addr, r4);
                bf[2 * ni][0]     = r4[0];
                bf[2 * ni][1]     = r4[1];
                bf[2 * ni + 1][0] = r4[2];
                bf[2 * ni + 1][1] = r4[3];
            }
            #pragma unroll
            for (int mi = 0; mi < 2; mi++)
                #pragma unroll
                for (int nj = 0; nj < 8; nj++)
                    mma16816(acc[mi][nj], af[mi], bf[nj]);
        }
        if (++slot >= 3) slot = 0;
    }

    // ---- epilogue ----
    const int which = nbase >> 10;
    const float* bias = (mode == 0) ? b0 : (which == 0 ? b0 : (which == 1 ? b1 : b2));
    const int qr = lane >> 2;
    const int qc = (lane & 3) * 2;
    #pragma unroll
    for (int mi = 0; mi < 2; mi++) {
        #pragma unroll
        for (int half = 0; half < 2; half++) {
            int m = mbase + wm * 32 + mi * 16 + qr + half * 8;
            int b_ = m >> 11, t = m & 2047;
            #pragma unroll
            for (int nj = 0; nj < 8; nj++) {
                int ng = nbase + wn * 64 + nj * 8 + qc;
                int n  = ng & 1023;
                float vx = acc[mi][nj][half * 2 + 0] + bias[n];
                float vy = acc[mi][nj][half * 2 + 1] + bias[n + 1];
                if (mode == 0) {
                    float2 o{vx, vy};
                    *reinterpret_cast<float2*>(out0 + (size_t)m * CDIM + n) = o;
                } else {
                    int h = n >> 6, d = n & 63;
                    size_t bht = ((size_t)(b_ * NHEAD + h)) * SEQ + t;
                    size_t base2 = bht * 128 + d;
                    if (which == 0) {
                        vx *= QSCALE; vy *= QSCALE;
                        uint32_t hp, lp;
                        split2(vx, vy, hp, lp);
                        *reinterpret_cast<uint32_t*>(q3 + base2)      = hp;
                        *reinterpret_cast<uint32_t*>(q3 + base2 + 64) = lp;
                    } else if (which == 1) {
                        float2 o{vx, vy};
                        *reinterpret_cast<float2*>(out0 + bht * HDIM + d) = o;
                        uint32_t hp, lp;
                        split2(vx, vy, hp, lp);
                        *reinterpret_cast<uint32_t*>(k3 + base2)      = hp;
                        *reinterpret_cast<uint32_t*>(k3 + base2 + 64) = lp;
                    } else {
                        float2 o{vx, vy};
                        *reinterpret_cast<float2*>(out1 + bht * HDIM + d) = o;
                        uint32_t hp, lp;
                        split2(vx, vy, hp, lp);
                        *reinterpret_cast<uint32_t*>(v2 + base2)      = hp;
                        *reinterpret_cast<uint32_t*>(v2 + base2 + 64) = lp;
                    }
                }
            }
        }
    }
}

// ---------------------------------------------------------------------------
// HMMA causal flash attention — NON-pipelined, 2 CTA/SM occupancy version.
// Max-free softmax, full 3-product S with fragment reuse (R14 math).
// Cross-CTA overlap replaces intra-CTA software pipelining: single S buffer,
// 2-slot K/V rings, smem 96KB, __launch_bounds__(256,2) (reg cap 128).
// BM=128 / BN=64, 256 threads. Epilogue writes (hi,lo,hi) rows of A3 [M][3072].
// smem: Q 2x16K | K ring 2x16K | V ring 2x16K = 96KB.
// ---------------------------------------------------------------------------
#define QS_OFF   0
#define KS_OFF   32768
#define VS_OFF   65536
#define ATTN_SMEM 98304

__global__ __launch_bounds__(256, 2) void attn_kernel(
    const __nv_bfloat16* __restrict__ Q3, const __nv_bfloat16* __restrict__ K3g,
    const __nv_bfloat16* __restrict__ V2, __nv_bfloat16* __restrict__ Yd)
{
    extern __shared__ char smem[];
    const uint32_t sm = smem_to_u32(smem);
    const uint32_t QS = sm + QS_OFF;
    const uint32_t KS = sm + KS_OFF;
    const uint32_t VS = sm + VS_OFF;

    const int tid = threadIdx.x;
    const int w = tid >> 5;
    const int lane = tid & 31;
    const int qt = (int)gridDim.x - 1 - (int)blockIdx.x;   // long CTAs first
    const int bh = blockIdx.y;
    const int qbase = qt * 128;

    const __nv_bfloat16* Qg = Q3 + ((size_t)bh * SEQ + qbase) * 128;
    const __nv_bfloat16* Kg = K3g + (size_t)bh * SEQ * 128;
    const __nv_bfloat16* Vg = V2 + (size_t)bh * SEQ * 128;

    auto load_q = [&]() {
        #pragma unroll
        for (int i = 0; i < 8; i++) {
            int g = tid + i * 256;          // 0..2047
            int r = g & 127, bc = g >> 7;   // bc 0..15
            int b = bc >> 3, c = bc & 7;
            const __nv_bfloat16* src = Qg + (size_t)r * 128 + b * 64 + c * 8;
            uint32_t dst = QS + b * 16384 + r * 128 + ((c ^ (r & 7)) << 4);
            CP_ASYNC16(dst, src);
        }
    };
    auto load_k = [&](int jt, int slot) {
        const __nv_bfloat16* base = Kg + (size_t)jt * 64 * 128;
        uint32_t kb = KS + slot * 16384;    // [kh 8K | kl 8K]
        #pragma unroll
        for (int i = 0; i < 4; i++) {
            int g = tid + i * 256;          // 0..1023
            int r = g >> 4, c = g & 15;
            const __nv_bfloat16* src = base + (size_t)r * 128 + c * 8;
            int cc = c & 7;
            uint32_t half = (c >> 3) * 8192;
            uint32_t dst = kb + half + r * 128 + ((cc ^ (r & 7)) << 4);
            CP_ASYNC16(dst, src);
        }
    };
    auto load_v = [&](int jt, int slot) {
        const __nv_bfloat16* base = Vg + (size_t)jt * 64 * 128;
        uint32_t vb = VS + slot * 16384;    // [vh 8K | vl 8K]
        #pragma unroll
        for (int i = 0; i < 4; i++) {
            int g = tid + i * 256;
            int r = g >> 4, c = g & 15;
            const __nv_bfloat16* src = base + (size_t)r * 128 + c * 8;
            int cc = c & 7;
            uint32_t half = (c >> 3) * 8192;
            uint32_t dst = vb + half + r * 128 + ((cc ^ (r & 7)) << 4);
            CP_ASYNC16(dst, src);
        }
    };

    float o[8][4];
    #pragma unroll
    for (int j = 0; j < 8; j++)
        #pragma unroll
        for (int q = 0; q < 4; q++) o[j][q] = 0.f;
    float li0 = 0.f, li1 = 0.f;     // per-thread partial row sums

    const int jmax = 2 * qt + 1;

    // S = qh.kh + ql.kh + qh.kl with K fragments loaded once per k-step
    auto mma_S = [&](float (&sd)[8][4], int slot) {
        #pragma unroll
        for (int j = 0; j < 8; j++)
            #pragma unroll
            for (int q = 0; q < 4; q++) sd[j][q] = 0.f;
        const uint32_t kb = KS + slot * 16384;
        #pragma unroll
        for (int ks = 0; ks < 4; ks++) {
            uint32_t ah[4], al[4];
            {
                int row = w * 16 + (lane & 15);
                int chunk = 2 * ks + (lane >> 4);
                uint32_t qoff = row * 128 + ((chunk ^ (row & 7)) << 4);
                ldsm_x4(QS + qoff, ah);
                ldsm_x4(QS + 16384 + qoff, al);
            }
            uint32_t bf[8][2];
            // kh half: used by both ah and al
            #pragma unroll
            for (int ni = 0; ni < 4; ni++) {
                int row = ni * 16 + ((lane >> 4) << 3) + (lane & 7);
                int chunk = 2 * ks + ((lane >> 3) & 1);
                uint32_t r4[4];
                ldsm_x4(kb + row * 128 + ((chunk ^ (row & 7)) << 4), r4);
                bf[2 * ni][0] = r4[0]; bf[2 * ni][1] = r4[1];
                bf[2 * ni + 1][0] = r4[2]; bf[2 * ni + 1][1] = r4[3];
            }
            #pragma unroll
            for (int nj = 0; nj < 8; nj++) {
                mma16816(sd[nj], ah, bf[nj]);
                mma16816(sd[nj], al, bf[nj]);
            }
            // kl half: used by ah only
            #pragma unroll
            for (int ni = 0; ni < 4; ni++) {
                int row = ni * 16 + ((lane >> 4) << 3) + (lane & 7);
                int chunk = 2 * ks + ((lane >> 3) & 1);
                uint32_t r4[4];
                ldsm_x4(kb + 8192 + row * 128 + ((chunk ^ (row & 7)) << 4), r4);
                bf[2 * ni][0] = r4[0]; bf[2 * ni][1] = r4[1];
                bf[2 * ni + 1][0] = r4[2]; bf[2 * ni + 1][1] = r4[3];
            }
            #pragma unroll
            for (int nj = 0; nj < 8; nj++)
                mma16816(sd[nj], ah, bf[nj]);
        }
    };

    // softmax (max-free) + PV (full 3-pass split) for tile cj
    auto consume = [&](float (&s)[8][4], int cj) {
        if (cj * 64 + 63 > qbase + w * 16) {
            const int gr = qbase + w * 16 + (lane >> 2);
            const int cb = cj * 64 + 2 * (lane & 3);
            #pragma unroll
            for (int nj = 0; nj < 8; nj++) {
                int c0 = cb + nj * 8;
                if (c0 > gr)     s[nj][0] = -1e30f;
                if (c0 + 1 > gr) s[nj][1] = -1e30f;
                if (c0 > gr + 8)     s[nj][2] = -1e30f;
                if (c0 + 1 > gr + 8) s[nj][3] = -1e30f;
            }
        }
        #pragma unroll
        for (int nj = 0; nj < 8; nj++) {
            s[nj][0] = exp2f(s[nj][0]); li0 += s[nj][0];
            s[nj][1] = exp2f(s[nj][1]); li0 += s[nj][1];
            s[nj][2] = exp2f(s[nj][2]); li1 += s[nj][2];
            s[nj][3] = exp2f(s[nj][3]); li1 += s[nj][3];
        }
        const uint32_t vb = VS + (cj & 1) * 16384;
        #pragma unroll
        for (int kc = 0; kc < 4; kc++) {
            uint32_t ah[4], al[4];
            split2(s[2 * kc][0],     s[2 * kc][1],     ah[0], al[0]);
            split2(s[2 * kc][2],     s[2 * kc][3],     ah[1], al[1]);
            split2(s[2 * kc + 1][0], s[2 * kc + 1][1], ah[2], al[2]);
            split2(s[2 * kc + 1][2], s[2 * kc + 1][3], ah[3], al[3]);
            #pragma unroll
            for (int dj2 = 0; dj2 < 4; dj2++) {
                int mm = lane >> 3, j = lane & 7;
                int row = kc * 16 + (mm & 1) * 8 + j;
                int chunk = 2 * dj2 + (mm >> 1);
                uint32_t off = row * 128 + ((chunk ^ (row & 7)) << 4);
                uint32_t bh4[4], bl4[4];
                ldsm_x4_t(vb + off, bh4);
                ldsm_x4_t(vb + 8192 + off, bl4);
                mma16816(o[2 * dj2],     ah, &bh4[0]);
                mma16816(o[2 * dj2 + 1], ah, &bh4[2]);
                mma16816(o[2 * dj2],     al, &bh4[0]);
                mma16816(o[2 * dj2 + 1], al, &bh4[2]);
                mma16816(o[2 * dj2],     ah, &bl4[0]);
                mma16816(o[2 * dj2 + 1], ah, &bl4[2]);
            }
        }
    };

    // ---- non-pipelined mainloop: prefetch depth 1, 2-slot rings ----
    load_q(); load_k(0, 0); load_v(0, 0); CP_COMMIT();

    float s[8][4];
    for (int jt = 0; jt <= jmax; ++jt) {
        const int buf = jt & 1;
        CP_WAIT0();          // data for tile jt landed
        __syncthreads();     // all warps finished reading slot buf^1 (tile jt-1)
        if (jt < jmax) { load_k(jt + 1, buf ^ 1); load_v(jt + 1, buf ^ 1); CP_COMMIT(); }
        mma_S(s, buf);
        consume(s, jt);
    }

    // ---- single li reduction, normalize + store split-bf16 rows of A3 ----
    li0 += __shfl_xor_sync(0xffffffffu, li0, 1);
    li0 += __shfl_xor_sync(0xffffffffu, li0, 2);
    li1 += __shfl_xor_sync(0xffffffffu, li1, 1);
    li1 += __shfl_xor_sync(0xffffffffu, li1, 2);

    const int b_ = bh >> 4;
    const int h  = bh & 15;
    const float inv0 = 1.f / li0, inv1 = 1.f / li1;
    const int t0 = qbase + w * 16 + (lane >> 2);
    const int cb = h * HDIM + 2 * (lane & 3);
    const size_t m0 = (size_t)b_ * SEQ + t0;
    #pragma unroll
    for (int dj = 0; dj < 8; dj++) {
        int col = cb + dj * 8;
        uint32_t hp, lp;
        split2(o[dj][0] * inv0, o[dj][1] * inv0, hp, lp);
        __nv_bfloat16* p0 = Yd + m0 * K3 + col;
        *reinterpret_cast<uint32_t*>(p0)        = hp;
        *reinterpret_cast<uint32_t*>(p0 + 1024) = lp;
        *reinterpret_cast<uint32_t*>(p0 + 2048) = hp;
        split2(o[dj][2] * inv1, o[dj][3] * inv1, hp, lp);
        __nv_bfloat16* p1 = Yd + (m0 + 8) * K3 + col;
        *reinterpret_cast<uint32_t*>(p1)        = hp;
        *reinterpret_cast<uint32_t*>(p1 + 1024) = lp;
        *reinterpret_cast<uint32_t*>(p1 + 2048) = hp;
    }
}

// ---------------------------------------------------------------------------
// Launch graph
// d_in: x, Wq, bq, Wk, bk, Wv, bv, Wp, bp
// d_out: [ y | present_k | present_v ]
// ---------------------------------------------------------------------------
extern "C" void kernel_launch(void* const* d_in, const int* in_sizes, int n_in,
                              void* d_out, int out_size)
{
    const float* x  = (const float*)d_in[0];
    const float* Wq = (const float*)d_in[1];
    const float* bq = (const float*)d_in[2];
    const float* Wk = (const float*)d_in[3];
    const float* bk = (const float*)d_in[4];
    const float* Wv = (const float*)d_in[5];
    const float* bv = (const float*)d_in[6];
    const float* Wp = (const float*)d_in[7];
    const float* bp = (const float*)d_in[8];

    float* out  = (float*)d_out;
    float* kout = out + Y_ELEMS;
    float* vout = out + Y_ELEMS + KV_ELEMS;

    __nv_bfloat16 *a3 = nullptr, *w3 = nullptr, *q3 = nullptr, *k3 = nullptr, *v2 = nullptr;
    cudaGetSymbolAddress((void**)&a3, g_a3);
    cudaGetSymbolAddress((void**)&w3, g_w3);
    cudaGetSymbolAddress((void**)&q3, g_q3);
    cudaGetSymbolAddress((void**)&k3, g_k3);
    cudaGetSymbolAddress((void**)&v2, g_v2);

    cudaFuncSetAttribute(gemm_bf16_kernel,
                         cudaFuncAttributeMaxDynamicSharedMemorySize, GSM_TOTAL);
    cudaFuncSetAttribute(attn_kernel,
                         cudaFuncAttributeMaxDynamicSharedMemorySize, ATTN_SMEM);

    // All 4 weight conversions in ONE launch; x conversion separate.
    {
        int total2w = 4 * CDIM * 512;
        conv_split_w_kernel<<<total2w / 256, 256>>>(Wq, Wk, Wv, Wp, w3);
        int total2x = MROWS * 512;
        conv_split_x_kernel<<<(total2x + 255) / 256, 256>>>(x, a3, total2x);
    }

    // Fused QKV GEMM: N = 3072 over contiguous Wq|Wk|Wv (tile 128x128)
    gemm_bf16_kernel<<<dim3(24, MROWS / 128), 256, GSM_TOTAL>>>(
        a3, w3, bq, bk, bv, kout, vout, q3, k3, v2, 1);

    // Attention (2 CTA/SM, non-pipelined, full 3-product S with fragment reuse)
    attn_kernel<<<dim3(SEQ / 128, BATCH * NHEAD), 256, ATTN_SMEM>>>(q3, k3, v2, a3);

    // Output projection (mode 0)
    gemm_bf16_kernel<<<dim3(8, MROWS / 128), 256, GSM_TOTAL>>>(
        a3, w3 + 3 * (size_t)CDIM * K3, bp, nullptr, nullptr,
        out, nullptr, nullptr, nullptr, nullptr, 0);
}